// round 1
// baseline (speedup 1.0000x reference)
#include <cuda_runtime.h>
#include <cstdint>

// Per-row top-k masking: out[b,n,c] = x[b,n,c] if it is among the k largest
// (or smallest, if largest==0) of row [b,n,:], else 0.
// One warp per row of C=768 floats; exact 32-bit threshold via
// binary search on the top byte + ballot refinement of the low 24 bits.

#define FULL_MASK 0xFFFFFFFFu

constexpr int C_DIM  = 768;   // channels per row (from reference shapes)
constexpr int VPT    = 24;    // values per thread (768 / 32)
constexpr int V4     = 6;     // float4 loads per thread
constexpr int WARPS  = 8;     // warps (rows) per block
constexpr int CAND_CAP = 768; // worst-case candidates in one byte-bin

__device__ __forceinline__ unsigned f2ord(unsigned b) {
    // order-preserving float->u32: larger float => larger unsigned
    return b ^ (unsigned)(((int)b >> 31) | 0x80000000);
}
__device__ __forceinline__ unsigned ord2f(unsigned u) {
    // inverse transform
    return u ^ (unsigned)(0x80000000u | ~((unsigned)((int)u >> 31)));
}

__global__ __launch_bounds__(WARPS * 32)
void topk_mask_kernel(const float* __restrict__ x,
                      const int* __restrict__ kptr,
                      const int* __restrict__ lptr,
                      float* __restrict__ out,
                      int nrows)
{
    __shared__ unsigned s_cand[WARPS][CAND_CAP];
    __shared__ unsigned s_cnt[WARPS];

    const int warp = threadIdx.x >> 5;
    const int lane = threadIdx.x & 31;
    const int row  = blockIdx.x * WARPS + warp;
    if (row >= nrows) return;

    const int k       = *kptr;       // uniform load, L2/L1 cached
    const int largest = *lptr;
    const unsigned flip = largest ? 0u : 0xFFFFFFFFu;

    const float4* __restrict__ xin =
        reinterpret_cast<const float4*>(x + (size_t)row * C_DIM);
    float4* __restrict__ xout =
        reinterpret_cast<float4*>(out + (size_t)row * C_DIM);

    // ---- load + convert to ordered u32 ----
    unsigned u[VPT];
    #pragma unroll
    for (int i = 0; i < V4; i++) {
        float4 v = xin[lane + 32 * i];
        u[4*i+0] = f2ord(__float_as_uint(v.x)) ^ flip;
        u[4*i+1] = f2ord(__float_as_uint(v.y)) ^ flip;
        u[4*i+2] = f2ord(__float_as_uint(v.z)) ^ flip;
        u[4*i+3] = f2ord(__float_as_uint(v.w)) ^ flip;
    }

    if (lane == 0) s_cnt[warp] = 0;

    // ---- binary search for top byte d of the k-th largest value ----
    // f(t) = count(u >= t<<24); invariant: f(lo) >= k > f(hi)
    unsigned lo = 0, hi = 256;
    int flo = C_DIM, fhi = 0;
    #pragma unroll
    for (int it = 0; it < 8; it++) {
        unsigned mid = (lo + hi) >> 1;
        unsigned T = mid << 24;
        int c = 0;
        #pragma unroll
        for (int i = 0; i < VPT; i++) c += (u[i] >= T) ? 1 : 0;
        c = __reduce_add_sync(FULL_MASK, c);
        if (c >= k) { lo = mid; flo = c; }
        else        { hi = mid; fhi = c; }
    }
    const unsigned d = lo;          // top byte of k-th largest
    int r = k - fhi;                // rank within the d-bin (r-th largest)
    const int m = flo - fhi;        // number of candidates in the d-bin

    // ---- compact candidates (top byte == d) into shared memory ----
    __syncwarp();
    #pragma unroll
    for (int i = 0; i < VPT; i++) {
        if ((u[i] >> 24) == d) {
            unsigned p = atomicAdd(&s_cnt[warp], 1u);
            s_cand[warp][p] = u[i];
        }
    }
    __syncwarp();

    // ---- refine low 24 bits: radix-select bit loop over candidates ----
    unsigned cur = d << 24;
    const bool valid0 = (lane < m);
    const unsigned v0 = valid0 ? s_cand[warp][lane] : 0u;
    const bool big = (m > 32);      // warp-uniform
    #pragma unroll 1
    for (int b = 23; b >= 0; b--) {
        // pred: candidate matches decided high bits and has bit b set
        // (cur has zeros in bits b..0, so (v^cur)>>b == 1 iff both hold)
        int cl = (valid0 && (((v0 ^ cur) >> b) == 1u)) ? 1 : 0;
        if (big) {
            for (int j = 32 + lane; j < m; j += 32)
                cl += (((s_cand[warp][j] ^ cur) >> b) == 1u) ? 1 : 0;
        }
        int c = __reduce_add_sync(FULL_MASK, cl);
        if (c >= r) cur |= (1u << b);
        else        r -= c;
    }
    // cur == ordered-u32 value of the k-th largest element (exact)

    // ---- threshold and write back ----
    #pragma unroll
    for (int i = 0; i < V4; i++) {
        float4 o;
        o.x = (u[4*i+0] >= cur) ? __uint_as_float(ord2f(u[4*i+0] ^ flip)) : 0.0f;
        o.y = (u[4*i+1] >= cur) ? __uint_as_float(ord2f(u[4*i+1] ^ flip)) : 0.0f;
        o.z = (u[4*i+2] >= cur) ? __uint_as_float(ord2f(u[4*i+2] ^ flip)) : 0.0f;
        o.w = (u[4*i+3] >= cur) ? __uint_as_float(ord2f(u[4*i+3] ^ flip)) : 0.0f;
        xout[lane + 32 * i] = o;
    }
}

extern "C" void kernel_launch(void* const* d_in, const int* in_sizes, int n_in,
                              void* d_out, int out_size)
{
    const float* x    = (const float*)d_in[0];
    const int*   kptr = (const int*)d_in[1];
    const int*   lptr = (const int*)d_in[2];
    float* out = (float*)d_out;

    int nrows = in_sizes[0] / C_DIM;
    int blocks = (nrows + WARPS - 1) / WARPS;
    topk_mask_kernel<<<blocks, WARPS * 32>>>(x, kptr, lptr, out, nrows);
}

// round 2
// speedup vs baseline: 1.3127x; 1.3127x over previous
#include <cuda_runtime.h>
#include <cstdint>

// Per-row top-k masking (k largest or smallest along last axis kept, rest zeroed).
// One warp per row of C=768 floats.
// Phase 1: pack ordered top-bytes (SWAR), 8-step binary search on the byte of the
//          k-th value using per-word carry-out byte-compare + POPC + REDUX.
// Phase 2: compact the few candidates sharing that byte; resolve low 24 bits exactly.
// Phase 3: float-domain threshold pass (threshold is an exact data value).

#define FULL_MASK 0xFFFFFFFFu

constexpr int C_DIM  = 768;   // channels per row
constexpr int VPT    = 24;    // values per thread
constexpr int V4     = 6;     // float4 loads per thread (also packed words per thread)
constexpr int WARPS  = 8;     // rows per block
constexpr int CAND_CAP = 768; // worst-case candidates in one byte-bin

__device__ __forceinline__ unsigned f2ord(unsigned b) {
    return b ^ (unsigned)(((int)b >> 31) | 0x80000000);
}
__device__ __forceinline__ unsigned ord2f(unsigned u) {
    return u ^ (unsigned)(0x80000000u | ~((unsigned)((int)u >> 31)));
}

__global__ __launch_bounds__(WARPS * 32)
void topk_mask_kernel(const float* __restrict__ x,
                      const int* __restrict__ kptr,
                      const int* __restrict__ lptr,
                      float* __restrict__ out,
                      int nrows)
{
    __shared__ unsigned s_cand[WARPS][CAND_CAP];
    __shared__ unsigned s_cnt[WARPS];

    const int warp = threadIdx.x >> 5;
    const int lane = threadIdx.x & 31;
    const int row  = blockIdx.x * WARPS + warp;
    if (row >= nrows) return;

    const int k       = *kptr;
    const int largest = *lptr;
    const unsigned flip = largest ? 0u : 0xFFFFFFFFu;

    const float4* __restrict__ xin =
        reinterpret_cast<const float4*>(x + (size_t)row * C_DIM);
    float4* __restrict__ xout =
        reinterpret_cast<float4*>(out + (size_t)row * C_DIM);

    // ---- load raw floats (kept in registers for the whole kernel) ----
    float f[VPT];
    #pragma unroll
    for (int i = 0; i < V4; i++) {
        float4 v = xin[lane + 32 * i];
        f[4*i+0] = v.x; f[4*i+1] = v.y; f[4*i+2] = v.z; f[4*i+3] = v.w;
    }

    if (lane == 0) s_cnt[warp] = 0;

    // ---- pack ordered top-bytes of all 24 values into 6 words ----
    const unsigned H  = 0x80808080u;
    const unsigned NH = 0x7F7F7F7Fu;
    const unsigned HX = H ^ flip;          // fold sign-bias + flip into one xor
    unsigned p[V4], xm[V4];
    #pragma unroll
    for (int j = 0; j < V4; j++) {
        unsigned w0 = __float_as_uint(f[4*j+0]);
        unsigned w1 = __float_as_uint(f[4*j+1]);
        unsigned w2 = __float_as_uint(f[4*j+2]);
        unsigned w3 = __float_as_uint(f[4*j+3]);
        unsigned p01 = __byte_perm(w0, w1, 0x0073);   // [b3(w0), b3(w1), x, x]
        unsigned p23 = __byte_perm(w2, w3, 0x0073);
        unsigned pk  = __byte_perm(p01, p23, 0x5410); // [b3(w0..w3)]
        // ordered-byte transform per byte: pos -> b|0x80, neg -> ~b  (+ flip)
        unsigned s  = pk & H;
        unsigned mm = (s >> 7) * 0x7Fu;
        p[j]  = pk ^ mm ^ HX;
        xm[j] = p[j] & NH;                 // precompute for SWAR adds
    }

    // ---- binary search for the top byte d of the k-th largest ----
    // f(t) = count(topbyte >= t); invariant f(lo) >= k > f(hi)
    unsigned lo = 0, hi = 256;
    int flo = C_DIM, fhi = 0;
    #pragma unroll
    for (int it = 0; it < 8; it++) {
        unsigned mid  = (lo + hi) >> 1;          // always in [1,255]
        unsigned q    = (256u - mid) & 0xFFu;
        unsigned crep = q * 0x01010101u;
        unsigned cqm  = crep & NH;
        int cnt = 0;
        #pragma unroll
        for (int j = 0; j < V4; j++) {
            unsigned s = xm[j] + cqm;                              // carries into bit7
            unsigned g = (p[j] & crep) | ((p[j] ^ crep) & s);      // 1 LOP3
            cnt += __popc(g & H);                                  // byte-wise (x>=mid)
        }
        cnt = __reduce_add_sync(FULL_MASK, cnt);
        if (cnt >= k) { lo = mid; flo = cnt; }
        else          { hi = mid; fhi = cnt; }
    }
    const unsigned d = lo;
    int r = k - fhi;          // rank within the d-bin
    const int m = flo - fhi;  // candidates in the d-bin

    // ---- compact candidates (top byte == d) into shared memory ----
    __syncwarp();
    {
        const unsigned drep = d * 0x01010101u;
        #pragma unroll
        for (int j = 0; j < V4; j++) {
            unsigned z = p[j] ^ drep;
            unsigned y = (z - 0x01010101u) & ~z & H;  // nonzero iff some byte == d
            if (y) {
                #pragma unroll
                for (int b = 0; b < 4; b++) {
                    if (((z >> (8*b)) & 0xFFu) == 0u) {
                        unsigned bits = __float_as_uint(f[4*j+b]);
                        unsigned uu = f2ord(bits) ^ flip;
                        unsigned pos = atomicAdd(&s_cnt[warp], 1u);
                        s_cand[warp][pos] = uu;
                    }
                }
            }
        }
    }
    __syncwarp();

    // ---- refine low 24 bits exactly (radix-select over candidates) ----
    unsigned cur = d << 24;
    const bool valid0 = (lane < m);
    const unsigned v0 = valid0 ? s_cand[warp][lane] : 0u;
    const bool big = (m > 32);   // warp-uniform
    #pragma unroll 1
    for (int b = 23; b >= 0; b--) {
        int cl = (valid0 && (((v0 ^ cur) >> b) == 1u)) ? 1 : 0;
        if (big) {
            for (int j = 32 + lane; j < m; j += 32)
                cl += (((s_cand[warp][j] ^ cur) >> b) == 1u) ? 1 : 0;
        }
        int c = __reduce_add_sync(FULL_MASK, cl);
        if (c >= r) cur |= (1u << b);
        else        r -= c;
    }
    // cur == exact ordered(-with-flip) value of the k-th element

    // ---- float-domain threshold pass ----
    if (largest) {
        const float thr = __uint_as_float(ord2f(cur));
        #pragma unroll
        for (int i = 0; i < V4; i++) {
            float4 o;
            o.x = (f[4*i+0] >= thr) ? f[4*i+0] : 0.0f;
            o.y = (f[4*i+1] >= thr) ? f[4*i+1] : 0.0f;
            o.z = (f[4*i+2] >= thr) ? f[4*i+2] : 0.0f;
            o.w = (f[4*i+3] >= thr) ? f[4*i+3] : 0.0f;
            xout[lane + 32 * i] = o;
        }
    } else {
        const float thr = __uint_as_float(ord2f(~cur));
        #pragma unroll
        for (int i = 0; i < V4; i++) {
            float4 o;
            o.x = (f[4*i+0] <= thr) ? f[4*i+0] : 0.0f;
            o.y = (f[4*i+1] <= thr) ? f[4*i+1] : 0.0f;
            o.z = (f[4*i+2] <= thr) ? f[4*i+2] : 0.0f;
            o.w = (f[4*i+3] <= thr) ? f[4*i+3] : 0.0f;
            xout[lane + 32 * i] = o;
        }
    }
}

extern "C" void kernel_launch(void* const* d_in, const int* in_sizes, int n_in,
                              void* d_out, int out_size)
{
    const float* x    = (const float*)d_in[0];
    const int*   kptr = (const int*)d_in[1];
    const int*   lptr = (const int*)d_in[2];
    float* out = (float*)d_out;

    int nrows = in_sizes[0] / C_DIM;
    int blocks = (nrows + WARPS - 1) / WARPS;
    topk_mask_kernel<<<blocks, WARPS * 32>>>(x, kptr, lptr, out, nrows);
}

// round 3
// speedup vs baseline: 1.9371x; 1.4757x over previous
#include <cuda_runtime.h>
#include <cstdint>

// Per-row top-k masking (keep k largest/smallest along last axis, zero the rest).
// One warp per row of C=768 floats.
// Phase 1: SWAR byte-pack + 8-step binary search (dp4a-accumulated counts).
// Phase 2: scan-based candidate compaction (no atomics).
// Phase 3: rank-select among candidates: bitonic sort (m<=32), byte-stage + sort
//          (m<=128), strided bit-loop fallback (m>128, exact worst case).
// Phase 4: float-domain threshold pass.

#define FULL_MASK 0xFFFFFFFFu

constexpr int C_DIM  = 768;
constexpr int VPT    = 24;
constexpr int V4     = 6;
constexpr int WARPS  = 8;
constexpr int CAND_CAP = 768;

__device__ __forceinline__ unsigned f2ord(unsigned b) {
    return b ^ (unsigned)(((int)b >> 31) | 0x80000000);
}
__device__ __forceinline__ unsigned ord2f(unsigned u) {
    return u ^ (unsigned)(0x80000000u | ~((unsigned)((int)u >> 31)));
}

// Sort <=32 values (ascending) across the warp, return value of the r-th
// largest (1-based). Invalid lanes padded with 0 (minimum ordered value).
__device__ __forceinline__ unsigned warp_rank_select(const unsigned* cand,
                                                     int m, int r, int lane)
{
    unsigned v = (lane < m) ? cand[lane] : 0u;
    #pragma unroll
    for (int size = 2; size <= 32; size <<= 1) {
        #pragma unroll
        for (int stride = size >> 1; stride > 0; stride >>= 1) {
            unsigned o = __shfl_xor_sync(FULL_MASK, v, stride);
            bool tm = (((lane & stride) != 0) ^ ((lane & size) != 0));
            unsigned mx = v > o ? v : o;
            unsigned mn = v > o ? o : v;
            v = tm ? mx : mn;
        }
    }
    return __shfl_sync(FULL_MASK, v, 32 - r);
}

__global__ __launch_bounds__(WARPS * 32)
void topk_mask_kernel(const float* __restrict__ x,
                      const int* __restrict__ kptr,
                      const int* __restrict__ lptr,
                      float* __restrict__ out,
                      int nrows)
{
    __shared__ unsigned s_cand[WARPS][CAND_CAP];

    const int warp = threadIdx.x >> 5;
    const int lane = threadIdx.x & 31;
    const int row  = blockIdx.x * WARPS + warp;
    if (row >= nrows) return;

    const int k       = *kptr;
    const int largest = *lptr;
    const unsigned flip = largest ? 0u : 0xFFFFFFFFu;

    const float4* __restrict__ xin =
        reinterpret_cast<const float4*>(x + (size_t)row * C_DIM);
    float4* __restrict__ xout =
        reinterpret_cast<float4*>(out + (size_t)row * C_DIM);

    // ---- load raw floats ----
    float f[VPT];
    #pragma unroll
    for (int i = 0; i < V4; i++) {
        float4 v = xin[lane + 32 * i];
        f[4*i+0] = v.x; f[4*i+1] = v.y; f[4*i+2] = v.z; f[4*i+3] = v.w;
    }

    // ---- pack ordered top-bytes into 6 words ----
    const unsigned H  = 0x80808080u;
    const unsigned NH = 0x7F7F7F7Fu;
    const unsigned HX = H ^ flip;
    unsigned p[V4], xm[V4];
    #pragma unroll
    for (int j = 0; j < V4; j++) {
        unsigned w0 = __float_as_uint(f[4*j+0]);
        unsigned w1 = __float_as_uint(f[4*j+1]);
        unsigned w2 = __float_as_uint(f[4*j+2]);
        unsigned w3 = __float_as_uint(f[4*j+3]);
        unsigned p01 = __byte_perm(w0, w1, 0x0073);
        unsigned p23 = __byte_perm(w2, w3, 0x0073);
        unsigned pk  = __byte_perm(p01, p23, 0x5410);
        unsigned s   = pk & H;
        unsigned mm  = (s >> 7) * 0x7Fu;
        p[j]  = pk ^ mm ^ HX;
        xm[j] = p[j] & NH;
    }

    // ---- 8-step binary search on the top byte (dp4a-accumulated counts) ----
    unsigned lo = 0, hi = 256;
    int flo = C_DIM, fhi = 0;
    #pragma unroll
    for (int it = 0; it < 8; it++) {
        unsigned mid  = (lo + hi) >> 1;              // in [1,255]
        unsigned crep = (256u - mid) * 0x01010101u;
        unsigned cqm  = crep & NH;
        unsigned acc  = 0;
        #pragma unroll
        for (int j = 0; j < V4; j++) {
            unsigned s = xm[j] + cqm;                          // carries into bit7
            unsigned g = (p[j] & crep) | ((p[j] ^ crep) & s);  // single LOP3
            acc = __dp4a(g & H, 0x01010101u, acc);             // += 0x80 per match
        }
        int cnt = __reduce_add_sync(FULL_MASK, (int)acc) >> 7;
        if (cnt >= k) { lo = mid; flo = cnt; }
        else          { hi = mid; fhi = cnt; }
    }
    const unsigned d = lo;
    int r = k - fhi;           // rank of k-th value inside the d-bin (1-based)
    int m = flo - fhi;         // bin population

    // ---- exact per-byte equality masks + scan-based compaction ----
    const unsigned drep = d * 0x01010101u;
    const unsigned dr7  = drep & NH;
    unsigned ym[V4];
    int ci = 0;
    #pragma unroll
    for (int j = 0; j < V4; j++) {
        unsigned z = p[j] ^ drep;
        unsigned a = (xm[j] ^ dr7) + NH;         // (z & NH) + NH, no cross-byte carry
        unsigned y = ~(a | z) & H;               // exact: 0x80 per zero byte of z
        ym[j] = y;
        ci += __popc(y);
    }
    int sc = ci;
    #pragma unroll
    for (int sh = 1; sh < 32; sh <<= 1) {
        int t = __shfl_up_sync(FULL_MASK, sc, sh);
        if (lane >= sh) sc += t;
    }
    int excl = sc - ci;
    unsigned* cand = s_cand[warp];
    {
        int pos = excl;
        #pragma unroll
        for (int j = 0; j < V4; j++) {
            unsigned y = ym[j];
            if (y) {
                #pragma unroll
                for (int b = 0; b < 4; b++) {
                    if (y & (0x80u << (8*b))) {
                        cand[pos++] = f2ord(__float_as_uint(f[4*j+b])) ^ flip;
                    }
                }
            }
        }
    }
    __syncwarp();

    // ---- rank-select the r-th largest among the m candidates ----
    unsigned cur = d << 24;
    unsigned thr_ord;

    if (m <= 32) {
        thr_ord = warp_rank_select(cand, m, r, lane);
    } else if (m <= 128) {
        int bse = 0;
        int bi  = 2;
        while (m > 32 && bi >= 0) {
            const int W = (m + 31) >> 5;     // <= 4
            int cb[4];
            #pragma unroll
            for (int j = 0; j < 4; j++) {
                int idx = lane + 32 * j;
                cb[j] = (j < W && idx < m)
                      ? (int)((cand[bse + idx] >> (8*bi)) & 0xFFu) : -1;
            }
            unsigned lo2 = 0, hi2 = 256;
            int flo2 = m, fhi2 = 0;
            #pragma unroll
            for (int it = 0; it < 8; it++) {
                int mid = (int)((lo2 + hi2) >> 1);
                int c = 0;
                #pragma unroll
                for (int j = 0; j < 4; j++) c += (cb[j] >= mid) ? 1 : 0;
                c = __reduce_add_sync(FULL_MASK, c);
                if (c >= r) { lo2 = mid; flo2 = c; }
                else        { hi2 = mid; fhi2 = c; }
            }
            const int d2 = (int)lo2;
            const int m2 = flo2 - fhi2;
            r  -= fhi2;
            cur |= ((unsigned)d2) << (8*bi);
            // compact survivors into the other smem region (disjoint: m<=128)
            int fl[4]; int c2 = 0;
            #pragma unroll
            for (int j = 0; j < 4; j++) { fl[j] = (cb[j] == d2); c2 += fl[j]; }
            int s2 = c2;
            #pragma unroll
            for (int sh = 1; sh < 32; sh <<= 1) {
                int t = __shfl_up_sync(FULL_MASK, s2, sh);
                if (lane >= sh) s2 += t;
            }
            int pos = ((bse == 0) ? 512 : 0) + (s2 - c2);
            #pragma unroll
            for (int j = 0; j < 4; j++) {
                if (fl[j]) cand[pos++] = cand[bse + lane + 32*j];
            }
            __syncwarp();
            bse = (bse == 0) ? 512 : 0;
            m = m2; bi--;
        }
        if (m <= 32) thr_ord = warp_rank_select(cand + bse, m, r, lane);
        else         thr_ord = cur;   // all 4 bytes fixed: remaining all equal
    } else {
        // rare heavy bin: exact strided bit-loop over low 24 bits
        const bool valid0 = (lane < m);
        const unsigned v0 = valid0 ? cand[lane] : 0u;
        #pragma unroll 1
        for (int b = 23; b >= 0; b--) {
            int cl = (valid0 && (((v0 ^ cur) >> b) == 1u)) ? 1 : 0;
            for (int j = 32 + lane; j < m; j += 32)
                cl += (((cand[j] ^ cur) >> b) == 1u) ? 1 : 0;
            int c = __reduce_add_sync(FULL_MASK, cl);
            if (c >= r) cur |= (1u << b);
            else        r -= c;
        }
        thr_ord = cur;
    }

    // ---- float-domain threshold pass ----
    if (largest) {
        const float thr = __uint_as_float(ord2f(thr_ord));
        #pragma unroll
        for (int i = 0; i < V4; i++) {
            float4 o;
            o.x = (f[4*i+0] >= thr) ? f[4*i+0] : 0.0f;
            o.y = (f[4*i+1] >= thr) ? f[4*i+1] : 0.0f;
            o.z = (f[4*i+2] >= thr) ? f[4*i+2] : 0.0f;
            o.w = (f[4*i+3] >= thr) ? f[4*i+3] : 0.0f;
            xout[lane + 32 * i] = o;
        }
    } else {
        const float thr = __uint_as_float(ord2f(thr_ord ^ flip));
        #pragma unroll
        for (int i = 0; i < V4; i++) {
            float4 o;
            o.x = (f[4*i+0] <= thr) ? f[4*i+0] : 0.0f;
            o.y = (f[4*i+1] <= thr) ? f[4*i+1] : 0.0f;
            o.z = (f[4*i+2] <= thr) ? f[4*i+2] : 0.0f;
            o.w = (f[4*i+3] <= thr) ? f[4*i+3] : 0.0f;
            xout[lane + 32 * i] = o;
        }
    }
}

extern "C" void kernel_launch(void* const* d_in, const int* in_sizes, int n_in,
                              void* d_out, int out_size)
{
    const float* x    = (const float*)d_in[0];
    const int*   kptr = (const int*)d_in[1];
    const int*   lptr = (const int*)d_in[2];
    float* out = (float*)d_out;

    int nrows = in_sizes[0] / C_DIM;
    int blocks = (nrows + WARPS - 1) / WARPS;
    topk_mask_kernel<<<blocks, WARPS * 32>>>(x, kptr, lptr, out, nrows);
}